// round 7
// baseline (speedup 1.0000x reference)
#include <cuda_runtime.h>
#include <cuda_bf16.h>
#include <math_constants.h>

// RoI max pooling (Caffe-style), bit-matching the JAX/XLA:CPU reference:
// bh/bw computed as roi_h * (1.0f/7.0f) (fast-math reciprocal-multiply, as
// XLA:CPU emits), all other boundary ops exact IEEE (__fmul_rn, rintf,
// floorf/ceilf). DO NOT change this arithmetic — verified bit-exact in R6.
//
// Layout: one WARP per (roi n, channel c). Per ph-bin: lanes load the RoI
// column range coalesced, vertical-max into smem rowmax, then lanes 0..6
// reduce their pw windows. This replaces scattered per-bin scalar loads
// (L1=61.7% wavefront-bound at 41us) with coalesced loads + full reuse.

#define CROP_H 7
#define CROP_W 7

__global__ __launch_bounds__(256)
void roipool_warp_kernel(const float* __restrict__ data,
                         const float* __restrict__ rois,
                         const int*   __restrict__ roibatches,
                         const float* __restrict__ scale_ptr,
                         float* __restrict__ out,
                         int C, int H, int W, int npairs)
{
    __shared__ float s_rowmax[8][64];   // one 64-wide rowmax per warp

    int warp_global = (blockIdx.x * blockDim.x + threadIdx.x) >> 5;
    if (warp_global >= npairs) return;
    int lane       = threadIdx.x & 31;
    int warp_local = threadIdx.x >> 5;

    int n = warp_global / C;
    int c = warp_global % C;

    float scale = __ldg(scale_ptr);
    float x1 = __ldg(&rois[n * 4 + 0]);
    float y1 = __ldg(&rois[n * 4 + 1]);
    float x2 = __ldg(&rois[n * 4 + 2]);
    float y2 = __ldg(&rois[n * 4 + 3]);

    int rsw = (int)rintf(__fmul_rn(x1, scale));
    int rsh = (int)rintf(__fmul_rn(y1, scale));
    int rew = (int)rintf(__fmul_rn(x2, scale));
    int reh = (int)rintf(__fmul_rn(y2, scale));

    float roi_h = (float)max(reh - rsh + 1, 1);
    float roi_w = (float)max(rew - rsw + 1, 1);

    // XLA:CPU fast-math form — verified bit-exact. Do not alter.
    const float RCP7 = 1.0f / 7.0f;
    float bh = __fmul_rn(roi_h, RCP7);
    float bw = __fmul_rn(roi_w, RCP7);

    // Horizontal coverage across all pw bins: [wlo, whi)
    // wlo == wstart(pw=0), whi == wend(pw=6), computed with identical formulas.
    int wlo = min(max(rsw, 0), W);   // floor(0*bw)=0
    int whi = min(max((int)ceilf(__fmul_rn(7.0f, bw)) + rsw, 0), W);

    int b = __ldg(&roibatches[n]);
    const float* plane = data + ((size_t)b * C + c) * (size_t)(H * W);

    float* rm = s_rowmax[warp_local];
    int w0 = wlo + lane;
    int w1 = w0 + 32;

    #pragma unroll
    for (int ph = 0; ph < CROP_H; ++ph) {
        int hstart = (int)floorf(__fmul_rn((float)ph, bh)) + rsh;
        int hend   = (int)ceilf (__fmul_rn((float)ph + 1.0f, bh)) + rsh;
        hstart = min(max(hstart, 0), H);
        hend   = min(max(hend,   0), H);

        // Coalesced vertical max over this bin's rows.
        float m0 = -CUDART_INF_F, m1 = -CUDART_INF_F;
        for (int h = hstart; h < hend; ++h) {
            const float* row = plane + (size_t)h * W;
            if (w0 < whi) m0 = fmaxf(m0, __ldg(row + w0));
            if (w1 < whi) m1 = fmaxf(m1, __ldg(row + w1));
        }

        __syncwarp();                 // previous iteration's readers done
        if (w0 < whi) rm[lane]      = m0;
        if (w1 < whi) rm[lane + 32] = m1;
        __syncwarp();

        if (lane < CROP_W) {
            int pw = lane;
            int wstart = (int)floorf(__fmul_rn((float)pw, bw)) + rsw;
            int wend   = (int)ceilf (__fmul_rn((float)pw + 1.0f, bw)) + rsw;
            wstart = min(max(wstart, 0), W);
            wend   = min(max(wend,   0), W);

            bool empty = (hend <= hstart) || (wend <= wstart);
            float m = -CUDART_INF_F;
            for (int w = wstart; w < wend; ++w)
                m = fmaxf(m, rm[w - wlo]);

            out[((size_t)(n * C + c) * CROP_H + ph) * CROP_W + pw]
                = empty ? 0.0f : m;
        }
    }
}

extern "C" void kernel_launch(void* const* d_in, const int* in_sizes, int n_in,
                              void* d_out, int out_size)
{
    const float* data      = nullptr;
    const float* rois      = nullptr;
    const int*   batches   = nullptr;
    const float* scale_ptr = nullptr;

    int data_elems = 0;
    for (int i = 0; i < n_in; ++i) {
        int sz = in_sizes[i];
        if (sz == 1)            scale_ptr = (const float*)d_in[i];
        else if (sz == 128)     batches   = (const int*)d_in[i];
        else if (sz == 512)     rois      = (const float*)d_in[i];
        else {                  data      = (const float*)d_in[i];
                                data_elems = sz; }
    }

    float* out = (float*)d_out;

    const int H = 64, W = 64, B = 4;
    int C = data_elems / (B * H * W);      // 256
    int N = 128;
    int npairs = N * C;                    // 32768 warps

    int threads = 256;                     // 8 warps/block
    int blocks = (npairs * 32 + threads - 1) / threads;   // 4096
    roipool_warp_kernel<<<blocks, threads>>>(data, rois, batches, scale_ptr,
                                             out, C, H, W, npairs);
}